// round 10
// baseline (speedup 1.0000x reference)
#include <cuda_runtime.h>
#include <cstdint>

// Problem constants
#define B_   4
#define T_   2048
#define D_   768
#define H_   12
#define DH_  64
#define M_   (B_ * T_)     // 8192 rows

// Scratch (allocation-free: __device__ globals)
__device__ float g_q[B_ * H_ * T_ * DH_];   // [B,H,T,Dh]
__device__ float g_k[B_ * H_ * T_ * DH_];
__device__ float g_v[B_ * H_ * T_ * DH_];
__device__ float g_y[B_ * T_ * D_];         // [B,T,D] attention output

__device__ __forceinline__ uint32_t tf32_rna(float x) {
    uint32_t y;
    asm("cvt.rna.tf32.f32 %0, %1;" : "=r"(y) : "f"(x));
    return y;
}

__device__ __forceinline__ float ex2f(float x) {
    float y;
    asm("ex2.approx.f32 %0, %1;" : "=f"(y) : "f"(x));
    return y;
}

__device__ __forceinline__ void mma_tf32(float d[4], const uint32_t a[4],
                                         const uint32_t b[2]) {
    asm volatile(
        "mma.sync.aligned.m16n8k8.row.col.f32.tf32.tf32.f32 "
        "{%0,%1,%2,%3}, {%4,%5,%6,%7}, {%8,%9}, {%0,%1,%2,%3};"
        : "+f"(d[0]), "+f"(d[1]), "+f"(d[2]), "+f"(d[3])
        : "r"(a[0]), "r"(a[1]), "r"(a[2]), "r"(a[3]), "r"(b[0]), "r"(b[1]));
}

// ---------------------------------------------------------------------------
// TF32 mma.sync GEMM v3: C[M,N] = A[M,K] @ W[N,K]^T + bias.
// 256 thr (8 warps), tile 128x128, warp tile 64x32, KC=32 double-buffered,
// 2 CTAs/SM.
//
// smem layout (per row, LDT=48 words, ≡16 mod 32):
//   k lives in 16-k groups g=k>>4; within a group, base slot
//   4*(k&3) + ((k>>2)&3), rotated by +4*(row&3) mod 16.
//   -> fragment loads: one LDS.128 per row per group = k{lc,lc+4,lc+8,lc+12}
//      (a-frags for TWO mma steps), quarter-warp banks 16(lr&1)+4lc+rot:
//      perfect 32-bank cover, conflict-free.
//   -> stores: 4 STS.64 per 8-k chunk, pair (k=c, k=c+4) at slot
//      (4c + 2(kg&1) + rot) & 15; 16-lane phase covers all 16 even banks:
//      conflict-free, static data indices.
// mode 0: fused QKV (blockIdx.z picks W/bias, scatter to g_q/g_k/g_v)
// mode 3: A = g_y, out = outext row-major.
// ---------------------------------------------------------------------------
#define KC        32
#define LDT       48
#define TILE_W    (128 * LDT)             // 6144 words
#define BUF_W     (2 * TILE_W)
#define NITER     (D_ / KC)               // 24
#define GEMM_SMEM (2 * BUF_W * 4)         // 98304 B

__global__ __launch_bounds__(256, 2) void gemm_tf32(
    const float* __restrict__ Aext,
    const float* __restrict__ W0, const float* __restrict__ W1,
    const float* __restrict__ W2,
    const float* __restrict__ bias0, const float* __restrict__ bias1,
    const float* __restrict__ bias2,
    float* __restrict__ outext, int mode)
{
    extern __shared__ uint32_t sm[];

    const int tid  = threadIdx.x;
    const int wid  = tid >> 5;
    const int lane = tid & 31;
    const int lr   = lane >> 2;
    const int lc   = lane & 3;
    const int warp_m = wid >> 2;
    const int warp_n = wid & 3;
    const int m0 = blockIdx.y * 128;
    const int n0 = blockIdx.x * 128;
    const int z  = blockIdx.z;

    const float* W    = (z == 0) ? W0 : (z == 1) ? W1 : W2;
    const float* bias = (z == 0) ? bias0 : (z == 1) ? bias1 : bias2;
    const float* A    = (mode == 3) ? g_y : Aext;

    const float* Ap = A + (size_t)m0 * D_;
    const float* Wp = W + (size_t)n0 * D_;

    // load geometry: row = tid>>2 (+64 per half), kg = tid&3 (8-k chunk)
    const int row_ld = tid >> 2;
    const int kg_ld  = tid & 3;
    const int g_st   = kg_ld >> 1;        // 16-k group this thread fills
    const int kgp_st = kg_ld & 1;         // parity within group

    float d[4][4][4];
    #pragma unroll
    for (int mi = 0; mi < 4; mi++)
        #pragma unroll
        for (int ni = 0; ni < 4; ni++)
            #pragma unroll
            for (int r = 0; r < 4; r++) d[mi][ni][r] = 0.0f;

    float4 sa0, sa1, sw0, sw1;            // 16-float staging (one half)

    auto ldg_half = [&](int it, int i) {
        const int row = row_ld + i * 64;
        const size_t goff = (size_t)row * D_ + it * KC + kg_ld * 8;
        const float* pa = Ap + goff;
        const float* pw = Wp + goff;
        sa0 = *(const float4*)pa;  sa1 = *(const float4*)(pa + 4);
        sw0 = *(const float4*)pw;  sw1 = *(const float4*)(pw + 4);
    };

    auto sts_half = [&](int buf, int i) {
        const int row = row_ld + i * 64;
        const int rot = (row & 3) * 4;
        uint32_t* As = sm + buf * BUF_W + row * LDT + g_st * 16;
        uint32_t* Ws = As + TILE_W;
        const float av[8] = { sa0.x, sa0.y, sa0.z, sa0.w,
                              sa1.x, sa1.y, sa1.z, sa1.w };
        const float wv[8] = { sw0.x, sw0.y, sw0.z, sw0.w,
                              sw1.x, sw1.y, sw1.z, sw1.w };
        #pragma unroll
        for (int c = 0; c < 4; c++) {
            const int off = (4 * c + 2 * kgp_st + rot) & 15;
            *(uint2*)(As + off) = make_uint2(tf32_rna(av[c]), tf32_rna(av[c + 4]));
            *(uint2*)(Ws + off) = make_uint2(tf32_rna(wv[c]), tf32_rna(wv[c + 4]));
        }
    };

    // compute both mma steps of 16-k group g (kg = 2g, 2g+1)
    auto compute = [&](const uint32_t* As, const uint32_t* Ws, int g) {
        const int rot = (lr & 3) * 4;
        const int off = (4 * lc + rot) & 15;
        uint32_t aT[4][2][4];
        #pragma unroll
        for (int mi = 0; mi < 4; mi++) {
            const int rb = warp_m * 64 + mi * 16 + lr;
            uint4 t0 = *(const uint4*)(As + rb * LDT + g * 16 + off);
            uint4 t1 = *(const uint4*)(As + (rb + 8) * LDT + g * 16 + off);
            aT[mi][0][0] = t0.x; aT[mi][0][1] = t0.y;
            aT[mi][0][2] = t0.z; aT[mi][0][3] = t0.w;
            aT[mi][1][0] = t1.x; aT[mi][1][1] = t1.y;
            aT[mi][1][2] = t1.z; aT[mi][1][3] = t1.w;
        }
        #pragma unroll
        for (int ni = 0; ni < 4; ni++) {
            const int n = warp_n * 32 + ni * 8 + lr;
            uint4 bq = *(const uint4*)(Ws + n * LDT + g * 16 + off);
            uint32_t b0[2] = { bq.x, bq.y };
            uint32_t b1[2] = { bq.z, bq.w };
            #pragma unroll
            for (int mi = 0; mi < 4; mi++) {
                uint32_t a0[4] = { aT[mi][0][0], aT[mi][1][0],
                                   aT[mi][0][1], aT[mi][1][1] };
                mma_tf32(d[mi][ni], a0, b0);
            }
            #pragma unroll
            for (int mi = 0; mi < 4; mi++) {
                uint32_t a1[4] = { aT[mi][0][2], aT[mi][1][2],
                                   aT[mi][0][3], aT[mi][1][3] };
                mma_tf32(d[mi][ni], a1, b1);
            }
        }
    };

    // prologue: fill buffer 0
    ldg_half(0, 0); sts_half(0, 0);
    ldg_half(0, 1); sts_half(0, 1);
    __syncthreads();

    for (int it = 0; it < NITER; ++it) {
        const int cur = it & 1;
        const int nxt = cur ^ 1;
        const uint32_t* As = sm + cur * BUF_W;
        const uint32_t* Ws = As + TILE_W;
        const bool pf = (it + 1 < NITER);

        if (pf) ldg_half(it + 1, 0);
        compute(As, Ws, 0);
        if (pf) { sts_half(nxt, 0); ldg_half(it + 1, 1); }
        compute(As, Ws, 1);
        if (pf) sts_half(nxt, 1);
        __syncthreads();
    }

    // Epilogue: +bias, scatter (fragment layout unchanged)
    #pragma unroll
    for (int ni = 0; ni < 4; ni++) {
        const int c  = n0 + warp_n * 32 + ni * 8 + 2 * lc;
        const float b0 = __ldg(bias + c);
        const float b1 = __ldg(bias + c + 1);
        #pragma unroll
        for (int mi = 0; mi < 4; mi++) {
            #pragma unroll
            for (int half = 0; half < 2; half++) {
                const int m = m0 + warp_m * 64 + mi * 16 + half * 8 + lr;
                float2 r;
                r.x = d[mi][ni][half * 2 + 0] + b0;
                r.y = d[mi][ni][half * 2 + 1] + b1;
                float* op;
                if (mode == 3) {
                    op = outext + (size_t)m * D_ + c;
                } else {
                    const int bb = m / T_;
                    const int t  = m % T_;
                    const int h  = c / DH_;
                    const int dh = c % DH_;
                    float* base = (z == 0) ? g_q : (z == 1) ? g_k : g_v;
                    op = base + (((size_t)(bb * H_ + h)) * T_ + t) * DH_ + dh;
                }
                *(float2*)op = r;
            }
        }
    }
}

// ---------------------------------------------------------------------------
// Tensor-core causal flash attention, v3 (unchanged — known good, R8).
// ---------------------------------------------------------------------------
#define FA_LD    72
#define FA_KS_W  (64 * FA_LD)
#define FA_SMEM  (2 * FA_KS_W * 4)
#define CEXP     0.1803368801111244f      // 0.125 * log2(e)

__global__ __launch_bounds__(256, 2) void flash_attn_tc()
{
    extern __shared__ uint32_t fsm[];
    uint32_t* Ks = fsm;                   // keys psi-permuted, dh interleaved
    uint32_t* Vs = fsm + FA_KS_W;         // [key][dh] natural

    const int tid  = threadIdx.x;
    const int wid  = tid >> 5;
    const int lane = tid & 31;
    const int lr   = lane >> 2;
    const int lc   = lane & 3;

    const int bh = blockIdx.y;
    const int q0 = blockIdx.x * 128;
    const int qr0 = q0 + wid * 16;
    const int r0 = qr0 + lr;
    const int r1 = r0 + 8;

    const float* Qb = g_q + (size_t)bh * T_ * DH_;
    const float* Kb = g_k + (size_t)bh * T_ * DH_;
    const float* Vb = g_v + (size_t)bh * T_ * DH_;

    uint32_t q[8][4];
    #pragma unroll
    for (int ks = 0; ks < 8; ks++) {
        q[ks][0] = tf32_rna(Qb[(size_t)r0 * DH_ + ks * 8 + lc]);
        q[ks][1] = tf32_rna(Qb[(size_t)r1 * DH_ + ks * 8 + lc]);
        q[ks][2] = tf32_rna(Qb[(size_t)r0 * DH_ + ks * 8 + lc + 4]);
        q[ks][3] = tf32_rna(Qb[(size_t)r1 * DH_ + ks * 8 + lc + 4]);
    }

    float O[8][4];
    #pragma unroll
    for (int ni = 0; ni < 8; ni++)
        #pragma unroll
        for (int r = 0; r < 4; r++) O[ni][r] = 0.0f;

    float m0r = -1e30f, m1r = -1e30f;
    float l0 = 0.0f, l1 = 0.0f;

    const uint32_t* vb0 = Vs + lc * FA_LD + lr;
    const uint32_t* vb1 = Vs + (lc + 4) * FA_LD + lr;

    const int jend = q0 + 128;
    for (int j0 = 0; j0 < jend; j0 += 64) {
        __syncthreads();
        {
            const float* Kg = Kb + (size_t)j0 * DH_;
            const float* Vg = Vb + (size_t)j0 * DH_;
            #pragma unroll
            for (int i = 0; i < 4; i++) {
                const int f   = tid + i * 256;
                const int row = f >> 4;
                const int c4  = f & 15;
                float4 kv = *(const float4*)(Kg + row * DH_ + c4 * 4);
                const int rowp = (row & 56) | (((row & 3) << 1) | ((row & 7) >> 2));
                uint32_t* kb = Ks + rowp * FA_LD + (c4 >> 1) * 8 + (c4 & 1);
                kb[0] = tf32_rna(kv.x);
                kb[2] = tf32_rna(kv.y);
                kb[4] = tf32_rna(kv.z);
                kb[6] = tf32_rna(kv.w);
                float4 vv = *(const float4*)(Vg + row * DH_ + c4 * 4);
                *(uint4*)(Vs + row * FA_LD + c4 * 4) =
                    make_uint4(tf32_rna(vv.x), tf32_rna(vv.y),
                               tf32_rna(vv.z), tf32_rna(vv.w));
            }
        }
        __syncthreads();

        if (j0 > qr0 + 15) continue;

        float S[8][4];
        #pragma unroll
        for (int ni = 0; ni < 8; ni++) {
            S[ni][0] = S[ni][1] = S[ni][2] = S[ni][3] = 0.0f;
            #pragma unroll
            for (int ks = 0; ks < 8; ks++) {
                uint2 bv = *(const uint2*)(Ks + (ni * 8 + lr) * FA_LD
                                              + ks * 8 + 2 * lc);
                uint32_t b2[2] = { bv.x, bv.y };
                mma_tf32(S[ni], q[ks], b2);
            }
        }

        if (j0 + 63 > qr0) {
            #pragma unroll
            for (int ni = 0; ni < 8; ni++) {
                const int ka = j0 + ni * 8 + lc;
                const int kb2 = ka + 4;
                if (ka  > r0) S[ni][0] = -1e30f;
                if (kb2 > r0) S[ni][1] = -1e30f;
                if (ka  > r1) S[ni][2] = -1e30f;
                if (kb2 > r1) S[ni][3] = -1e30f;
            }
        }

        float m0n = m0r, m1n = m1r;
        #pragma unroll
        for (int ni = 0; ni < 8; ni++) {
            m0n = fmaxf(m0n, fmaxf(S[ni][0], S[ni][1]));
            m1n = fmaxf(m1n, fmaxf(S[ni][2], S[ni][3]));
        }
        m0n = fmaxf(m0n, __shfl_xor_sync(0xFFFFFFFFu, m0n, 1));
        m0n = fmaxf(m0n, __shfl_xor_sync(0xFFFFFFFFu, m0n, 2));
        m1n = fmaxf(m1n, __shfl_xor_sync(0xFFFFFFFFu, m1n, 1));
        m1n = fmaxf(m1n, __shfl_xor_sync(0xFFFFFFFFu, m1n, 2));

        const float sf0 = ex2f((m0r - m0n) * CEXP);
        const float sf1 = ex2f((m1r - m1n) * CEXP);
        m0r = m0n; m1r = m1n;
        l0 *= sf0; l1 *= sf1;
        #pragma unroll
        for (int ni = 0; ni < 8; ni++) {
            O[ni][0] *= sf0; O[ni][1] *= sf0;
            O[ni][2] *= sf1; O[ni][3] *= sf1;
        }

        const float mc0 = m0n * CEXP;
        const float mc1 = m1n * CEXP;
        #pragma unroll
        for (int ni = 0; ni < 8; ni++) {
            S[ni][0] = ex2f(fmaf(S[ni][0], CEXP, -mc0));
            S[ni][1] = ex2f(fmaf(S[ni][1], CEXP, -mc0));
            S[ni][2] = ex2f(fmaf(S[ni][2], CEXP, -mc1));
            S[ni][3] = ex2f(fmaf(S[ni][3], CEXP, -mc1));
            l0 += S[ni][0] + S[ni][1];
            l1 += S[ni][2] + S[ni][3];
        }

        #pragma unroll
        for (int ks = 0; ks < 8; ks++) {
            uint32_t a[4] = { tf32_rna(S[ks][0]), tf32_rna(S[ks][2]),
                              tf32_rna(S[ks][1]), tf32_rna(S[ks][3]) };
            #pragma unroll
            for (int ni = 0; ni < 8; ni++) {
                uint32_t b2[2] = { vb0[ks * 8 * FA_LD + ni * 8],
                                   vb1[ks * 8 * FA_LD + ni * 8] };
                mma_tf32(O[ni], a, b2);
            }
        }
    }

    l0 += __shfl_xor_sync(0xFFFFFFFFu, l0, 1);
    l0 += __shfl_xor_sync(0xFFFFFFFFu, l0, 2);
    l1 += __shfl_xor_sync(0xFFFFFFFFu, l1, 1);
    l1 += __shfl_xor_sync(0xFFFFFFFFu, l1, 2);
    const float inv0 = 1.0f / l0;
    const float inv1 = 1.0f / l1;

    const int b = bh / H_;
    const int h = bh % H_;
    float* y0 = g_y + ((size_t)(b * T_ + r0)) * D_ + h * DH_;
    float* y1 = g_y + ((size_t)(b * T_ + r1)) * D_ + h * DH_;
    #pragma unroll
    for (int ni = 0; ni < 8; ni++) {
        *(float2*)(y0 + ni * 8 + 2 * lc) = make_float2(O[ni][0] * inv0, O[ni][1] * inv0);
        *(float2*)(y1 + ni * 8 + 2 * lc) = make_float2(O[ni][2] * inv1, O[ni][3] * inv1);
    }
}

// ---------------------------------------------------------------------------
// Launch. Inputs (metadata order): x, Wq, bq, Wk, bk, Wv, bv, Wp, bp
// ---------------------------------------------------------------------------
extern "C" void kernel_launch(void* const* d_in, const int* in_sizes, int n_in,
                              void* d_out, int out_size)
{
    (void)in_sizes; (void)n_in; (void)out_size;
    const float* x  = (const float*)d_in[0];
    const float* Wq = (const float*)d_in[1];
    const float* bq = (const float*)d_in[2];
    const float* Wk = (const float*)d_in[3];
    const float* bk = (const float*)d_in[4];
    const float* Wv = (const float*)d_in[5];
    const float* bv = (const float*)d_in[6];
    const float* Wp = (const float*)d_in[7];
    const float* bp = (const float*)d_in[8];
    float* out = (float*)d_out;

    cudaFuncSetAttribute(gemm_tf32, cudaFuncAttributeMaxDynamicSharedMemorySize,
                         GEMM_SMEM);
    cudaFuncSetAttribute(flash_attn_tc, cudaFuncAttributeMaxDynamicSharedMemorySize,
                         FA_SMEM);

    // fused Q/K/V projections: blockIdx.z picks weights/bias/output
    gemm_tf32<<<dim3(D_ / 128, M_ / 128, 3), 256, GEMM_SMEM>>>(
        x, Wq, Wk, Wv, bq, bk, bv, nullptr, 0);

    flash_attn_tc<<<dim3(T_ / 128, B_ * H_), 256, FA_SMEM>>>();

    // output projection
    gemm_tf32<<<dim3(D_ / 128, M_ / 128, 1), 256, GEMM_SMEM>>>(
        nullptr, Wp, Wp, Wp, bp, bp, bp, out, 3);
}

// round 11
// speedup vs baseline: 1.1835x; 1.1835x over previous
#include <cuda_runtime.h>
#include <cstdint>

// Problem constants
#define B_   4
#define T_   2048
#define D_   768
#define H_   12
#define DH_  64
#define M_   (B_ * T_)     // 8192 rows

// Scratch (allocation-free: __device__ globals)
__device__ float g_q[B_ * H_ * T_ * DH_];   // [B,H,T,Dh]
__device__ float g_k[B_ * H_ * T_ * DH_];
__device__ float g_v[B_ * H_ * T_ * DH_];
__device__ float g_y[B_ * T_ * D_];         // [B,T,D] attention output

__device__ __forceinline__ uint32_t tf32_rna(float x) {
    uint32_t y;
    asm("cvt.rna.tf32.f32 %0, %1;" : "=r"(y) : "f"(x));
    return y;
}

__device__ __forceinline__ float ex2f(float x) {
    float y;
    asm("ex2.approx.f32 %0, %1;" : "=f"(y) : "f"(x));
    return y;
}

__device__ __forceinline__ void mma_tf32(float d[4], const uint32_t a[4],
                                         const uint32_t b[2]) {
    asm volatile(
        "mma.sync.aligned.m16n8k8.row.col.f32.tf32.tf32.f32 "
        "{%0,%1,%2,%3}, {%4,%5,%6,%7}, {%8,%9}, {%0,%1,%2,%3};"
        : "+f"(d[0]), "+f"(d[1]), "+f"(d[2]), "+f"(d[3])
        : "r"(a[0]), "r"(a[1]), "r"(a[2]), "r"(a[3]), "r"(b[0]), "r"(b[1]));
}

// ---------------------------------------------------------------------------
// TF32 mma.sync GEMM v4: C[M,N] = A[M,K] @ W[N,K]^T + bias.
// = R8's v2 structure (separate launches, 16-reg staging halves, 2 CTAs/SM)
// with LDT=40 (≡8 mod 32) + per-row xor-4 group swizzle:
//   word w of each 8-k group holds {k0,k4,k1,k5,k2,k6,k3,k7}[w ^ 4*(row&1)]
//   -> fragment LDS.64 (pair k=lc,k=lc+4 at word (2lc)^4(lr&1)):
//      half-warp banks 8lr + (2lc^4(lr&1)) = full even cover, conflict-free.
//   -> stores: 2 STS.128/chunk at word 0^x4 and 4^x4; 8-lane phases cover
//      quads {0,8,16,24}+{4,12,20,28}, conflict-free.
// smem 81.9 KB (x2 CTAs = 163.8 KB, leaves ~64 KB L1D for the LDG stream).
// mode 0/1/2: out scattered to g_q/g_k/g_v; mode 3: A=g_y, out=outext.
// ---------------------------------------------------------------------------
#define KC        32
#define LDT       40
#define TILE_W    (128 * LDT)             // 5120 words
#define BUF_W     (2 * TILE_W)
#define NITER     (D_ / KC)               // 24
#define GEMM_SMEM (2 * BUF_W * 4)         // 81920 B

__global__ __launch_bounds__(256, 2) void gemm_tf32(
    const float* __restrict__ Aext, const float* __restrict__ W,
    const float* __restrict__ bias, float* __restrict__ outext, int mode)
{
    extern __shared__ uint32_t sm[];

    const int tid  = threadIdx.x;
    const int wid  = tid >> 5;
    const int lane = tid & 31;
    const int lr   = lane >> 2;
    const int lc   = lane & 3;
    const int warp_m = wid >> 2;
    const int warp_n = wid & 3;
    const int m0 = blockIdx.y * 128;
    const int n0 = blockIdx.x * 128;

    const float* A  = (mode == 3) ? g_y : Aext;
    const float* Ap = A + (size_t)m0 * D_;
    const float* Wp = W + (size_t)n0 * D_;

    const int row_ld = tid >> 2;          // 0..63 (+64 second half)
    const int kg_ld  = tid & 3;           // 8-k chunk

    float d[4][4][4];
    #pragma unroll
    for (int mi = 0; mi < 4; mi++)
        #pragma unroll
        for (int ni = 0; ni < 4; ni++)
            #pragma unroll
            for (int r = 0; r < 4; r++) d[mi][ni][r] = 0.0f;

    float4 sa0, sa1, sw0, sw1;            // 16-float staging (one half)

    auto ldg_half = [&](int it, int i) {
        const int row = row_ld + i * 64;
        const size_t goff = (size_t)row * D_ + it * KC + kg_ld * 8;
        const float* pa = Ap + goff;
        const float* pw = Wp + goff;
        sa0 = *(const float4*)pa;  sa1 = *(const float4*)(pa + 4);
        sw0 = *(const float4*)pw;  sw1 = *(const float4*)(pw + 4);
    };
    // group words: {k0,k4,k1,k5} at 0^x4, {k2,k6,k3,k7} at 4^x4
    auto sts_half = [&](int buf, int i) {
        const int row = row_ld + i * 64;
        const int x4  = (row & 1) * 4;
        uint32_t* As = sm + buf * BUF_W + row * LDT + kg_ld * 8;
        uint32_t* Ws = As + TILE_W;
        *(uint4*)(As + (0 ^ x4)) = make_uint4(tf32_rna(sa0.x), tf32_rna(sa1.x),
                                              tf32_rna(sa0.y), tf32_rna(sa1.y));
        *(uint4*)(As + (4 ^ x4)) = make_uint4(tf32_rna(sa0.z), tf32_rna(sa1.z),
                                              tf32_rna(sa0.w), tf32_rna(sa1.w));
        *(uint4*)(Ws + (0 ^ x4)) = make_uint4(tf32_rna(sw0.x), tf32_rna(sw1.x),
                                              tf32_rna(sw0.y), tf32_rna(sw1.y));
        *(uint4*)(Ws + (4 ^ x4)) = make_uint4(tf32_rna(sw0.z), tf32_rna(sw1.z),
                                              tf32_rna(sw0.w), tf32_rna(sw1.w));
    };
    auto mma_step = [&](const uint32_t* As, const uint32_t* Ws, int kg) {
        const int woff = (2 * lc) ^ (4 * (lr & 1));   // pair slot in group
        uint32_t a[4][4], b[4][2];
        #pragma unroll
        for (int mi = 0; mi < 4; mi++) {
            const int base = (warp_m * 64 + mi * 16 + lr) * LDT + kg * 8 + woff;
            uint2 p0 = *(const uint2*)(As + base);
            uint2 p1 = *(const uint2*)(As + base + 8 * LDT);
            a[mi][0] = p0.x; a[mi][1] = p1.x; a[mi][2] = p0.y; a[mi][3] = p1.y;
        }
        #pragma unroll
        for (int ni = 0; ni < 4; ni++) {
            uint2 pb = *(const uint2*)(Ws + (warp_n * 32 + ni * 8 + lr) * LDT
                                          + kg * 8 + woff);
            b[ni][0] = pb.x; b[ni][1] = pb.y;
        }
        #pragma unroll
        for (int mi = 0; mi < 4; mi++)
            #pragma unroll
            for (int ni = 0; ni < 4; ni++)
                mma_tf32(d[mi][ni], a[mi], b[ni]);
    };

    // prologue: fill buffer 0
    ldg_half(0, 0); sts_half(0, 0);
    ldg_half(0, 1); sts_half(0, 1);
    __syncthreads();

    for (int it = 0; it < NITER; ++it) {
        const int cur = it & 1;
        const int nxt = cur ^ 1;
        const uint32_t* As = sm + cur * BUF_W;
        const uint32_t* Ws = As + TILE_W;
        const bool pf = (it + 1 < NITER);

        if (pf) ldg_half(it + 1, 0);
        mma_step(As, Ws, 0);
        mma_step(As, Ws, 1);
        if (pf) { sts_half(nxt, 0); ldg_half(it + 1, 1); }
        mma_step(As, Ws, 2);
        mma_step(As, Ws, 3);
        if (pf) sts_half(nxt, 1);
        __syncthreads();
    }

    // Epilogue: +bias, scatter
    #pragma unroll
    for (int ni = 0; ni < 4; ni++) {
        const int c  = n0 + warp_n * 32 + ni * 8 + 2 * lc;
        const float b0 = __ldg(bias + c);
        const float b1 = __ldg(bias + c + 1);
        #pragma unroll
        for (int mi = 0; mi < 4; mi++) {
            #pragma unroll
            for (int half = 0; half < 2; half++) {
                const int m = m0 + warp_m * 64 + mi * 16 + half * 8 + lr;
                float2 r;
                r.x = d[mi][ni][half * 2 + 0] + b0;
                r.y = d[mi][ni][half * 2 + 1] + b1;
                float* op;
                if (mode == 3) {
                    op = outext + (size_t)m * D_ + c;
                } else {
                    const int bb = m / T_;
                    const int t  = m % T_;
                    const int h  = c / DH_;
                    const int dh = c % DH_;
                    float* base = (mode == 0) ? g_q : (mode == 1) ? g_k : g_v;
                    op = base + (((size_t)(bb * H_ + h)) * T_ + t) * DH_ + dh;
                }
                *(float2*)op = r;
            }
        }
    }
}

// ---------------------------------------------------------------------------
// Tensor-core causal flash attention, v3 (R8 known-good) + reversed q-tile
// launch order: heavy diagonal blocks (large q0, most KV tiles) first,
// shrinking the last-wave tail.
// ---------------------------------------------------------------------------
#define FA_LD    72
#define FA_KS_W  (64 * FA_LD)
#define FA_SMEM  (2 * FA_KS_W * 4)
#define CEXP     0.1803368801111244f      // 0.125 * log2(e)

__global__ __launch_bounds__(256, 2) void flash_attn_tc()
{
    extern __shared__ uint32_t fsm[];
    uint32_t* Ks = fsm;                   // keys psi-permuted, dh interleaved
    uint32_t* Vs = fsm + FA_KS_W;         // [key][dh] natural

    const int tid  = threadIdx.x;
    const int wid  = tid >> 5;
    const int lane = tid & 31;
    const int lr   = lane >> 2;
    const int lc   = lane & 3;

    const int bh = blockIdx.y;
    const int q0 = ((int)gridDim.x - 1 - (int)blockIdx.x) * 128;  // heavy first
    const int qr0 = q0 + wid * 16;
    const int r0 = qr0 + lr;
    const int r1 = r0 + 8;

    const float* Qb = g_q + (size_t)bh * T_ * DH_;
    const float* Kb = g_k + (size_t)bh * T_ * DH_;
    const float* Vb = g_v + (size_t)bh * T_ * DH_;

    uint32_t q[8][4];
    #pragma unroll
    for (int ks = 0; ks < 8; ks++) {
        q[ks][0] = tf32_rna(Qb[(size_t)r0 * DH_ + ks * 8 + lc]);
        q[ks][1] = tf32_rna(Qb[(size_t)r1 * DH_ + ks * 8 + lc]);
        q[ks][2] = tf32_rna(Qb[(size_t)r0 * DH_ + ks * 8 + lc + 4]);
        q[ks][3] = tf32_rna(Qb[(size_t)r1 * DH_ + ks * 8 + lc + 4]);
    }

    float O[8][4];
    #pragma unroll
    for (int ni = 0; ni < 8; ni++)
        #pragma unroll
        for (int r = 0; r < 4; r++) O[ni][r] = 0.0f;

    float m0r = -1e30f, m1r = -1e30f;
    float l0 = 0.0f, l1 = 0.0f;

    const uint32_t* vb0 = Vs + lc * FA_LD + lr;
    const uint32_t* vb1 = Vs + (lc + 4) * FA_LD + lr;

    const int jend = q0 + 128;
    for (int j0 = 0; j0 < jend; j0 += 64) {
        __syncthreads();
        {
            const float* Kg = Kb + (size_t)j0 * DH_;
            const float* Vg = Vb + (size_t)j0 * DH_;
            #pragma unroll
            for (int i = 0; i < 4; i++) {
                const int f   = tid + i * 256;
                const int row = f >> 4;
                const int c4  = f & 15;
                float4 kv = *(const float4*)(Kg + row * DH_ + c4 * 4);
                const int rowp = (row & 56) | (((row & 3) << 1) | ((row & 7) >> 2));
                uint32_t* kb = Ks + rowp * FA_LD + (c4 >> 1) * 8 + (c4 & 1);
                kb[0] = tf32_rna(kv.x);
                kb[2] = tf32_rna(kv.y);
                kb[4] = tf32_rna(kv.z);
                kb[6] = tf32_rna(kv.w);
                float4 vv = *(const float4*)(Vg + row * DH_ + c4 * 4);
                *(uint4*)(Vs + row * FA_LD + c4 * 4) =
                    make_uint4(tf32_rna(vv.x), tf32_rna(vv.y),
                               tf32_rna(vv.z), tf32_rna(vv.w));
            }
        }
        __syncthreads();

        if (j0 > qr0 + 15) continue;

        float S[8][4];
        #pragma unroll
        for (int ni = 0; ni < 8; ni++) {
            S[ni][0] = S[ni][1] = S[ni][2] = S[ni][3] = 0.0f;
            #pragma unroll
            for (int ks = 0; ks < 8; ks++) {
                uint2 bv = *(const uint2*)(Ks + (ni * 8 + lr) * FA_LD
                                              + ks * 8 + 2 * lc);
                uint32_t b2[2] = { bv.x, bv.y };
                mma_tf32(S[ni], q[ks], b2);
            }
        }

        if (j0 + 63 > qr0) {
            #pragma unroll
            for (int ni = 0; ni < 8; ni++) {
                const int ka = j0 + ni * 8 + lc;
                const int kb2 = ka + 4;
                if (ka  > r0) S[ni][0] = -1e30f;
                if (kb2 > r0) S[ni][1] = -1e30f;
                if (ka  > r1) S[ni][2] = -1e30f;
                if (kb2 > r1) S[ni][3] = -1e30f;
            }
        }

        float m0n = m0r, m1n = m1r;
        #pragma unroll
        for (int ni = 0; ni < 8; ni++) {
            m0n = fmaxf(m0n, fmaxf(S[ni][0], S[ni][1]));
            m1n = fmaxf(m1n, fmaxf(S[ni][2], S[ni][3]));
        }
        m0n = fmaxf(m0n, __shfl_xor_sync(0xFFFFFFFFu, m0n, 1));
        m0n = fmaxf(m0n, __shfl_xor_sync(0xFFFFFFFFu, m0n, 2));
        m1n = fmaxf(m1n, __shfl_xor_sync(0xFFFFFFFFu, m1n, 1));
        m1n = fmaxf(m1n, __shfl_xor_sync(0xFFFFFFFFu, m1n, 2));

        const float sf0 = ex2f((m0r - m0n) * CEXP);
        const float sf1 = ex2f((m1r - m1n) * CEXP);
        m0r = m0n; m1r = m1n;
        l0 *= sf0; l1 *= sf1;
        #pragma unroll
        for (int ni = 0; ni < 8; ni++) {
            O[ni][0] *= sf0; O[ni][1] *= sf0;
            O[ni][2] *= sf1; O[ni][3] *= sf1;
        }

        const float mc0 = m0n * CEXP;
        const float mc1 = m1n * CEXP;
        #pragma unroll
        for (int ni = 0; ni < 8; ni++) {
            S[ni][0] = ex2f(fmaf(S[ni][0], CEXP, -mc0));
            S[ni][1] = ex2f(fmaf(S[ni][1], CEXP, -mc0));
            S[ni][2] = ex2f(fmaf(S[ni][2], CEXP, -mc1));
            S[ni][3] = ex2f(fmaf(S[ni][3], CEXP, -mc1));
            l0 += S[ni][0] + S[ni][1];
            l1 += S[ni][2] + S[ni][3];
        }

        #pragma unroll
        for (int ks = 0; ks < 8; ks++) {
            uint32_t a[4] = { tf32_rna(S[ks][0]), tf32_rna(S[ks][2]),
                              tf32_rna(S[ks][1]), tf32_rna(S[ks][3]) };
            #pragma unroll
            for (int ni = 0; ni < 8; ni++) {
                uint32_t b2[2] = { vb0[ks * 8 * FA_LD + ni * 8],
                                   vb1[ks * 8 * FA_LD + ni * 8] };
                mma_tf32(O[ni], a, b2);
            }
        }
    }

    l0 += __shfl_xor_sync(0xFFFFFFFFu, l0, 1);
    l0 += __shfl_xor_sync(0xFFFFFFFFu, l0, 2);
    l1 += __shfl_xor_sync(0xFFFFFFFFu, l1, 1);
    l1 += __shfl_xor_sync(0xFFFFFFFFu, l1, 2);
    const float inv0 = 1.0f / l0;
    const float inv1 = 1.0f / l1;

    const int b = bh / H_;
    const int h = bh % H_;
    float* y0 = g_y + ((size_t)(b * T_ + r0)) * D_ + h * DH_;
    float* y1 = g_y + ((size_t)(b * T_ + r1)) * D_ + h * DH_;
    #pragma unroll
    for (int ni = 0; ni < 8; ni++) {
        *(float2*)(y0 + ni * 8 + 2 * lc) = make_float2(O[ni][0] * inv0, O[ni][1] * inv0);
        *(float2*)(y1 + ni * 8 + 2 * lc) = make_float2(O[ni][2] * inv1, O[ni][3] * inv1);
    }
}

// ---------------------------------------------------------------------------
// Launch. Inputs (metadata order): x, Wq, bq, Wk, bk, Wv, bv, Wp, bp
// ---------------------------------------------------------------------------
extern "C" void kernel_launch(void* const* d_in, const int* in_sizes, int n_in,
                              void* d_out, int out_size)
{
    (void)in_sizes; (void)n_in; (void)out_size;
    const float* x  = (const float*)d_in[0];
    const float* Wq = (const float*)d_in[1];
    const float* bq = (const float*)d_in[2];
    const float* Wk = (const float*)d_in[3];
    const float* bk = (const float*)d_in[4];
    const float* Wv = (const float*)d_in[5];
    const float* bv = (const float*)d_in[6];
    const float* Wp = (const float*)d_in[7];
    const float* bp = (const float*)d_in[8];
    float* out = (float*)d_out;

    cudaFuncSetAttribute(gemm_tf32, cudaFuncAttributeMaxDynamicSharedMemorySize,
                         GEMM_SMEM);
    cudaFuncSetAttribute(flash_attn_tc, cudaFuncAttributeMaxDynamicSharedMemorySize,
                         FA_SMEM);

    dim3 gemm_grid(D_ / 128, M_ / 128);   // (6, 64)
    dim3 gemm_block(256);

    gemm_tf32<<<gemm_grid, gemm_block, GEMM_SMEM>>>(x, Wq, bq, nullptr, 0);
    gemm_tf32<<<gemm_grid, gemm_block, GEMM_SMEM>>>(x, Wk, bk, nullptr, 1);
    gemm_tf32<<<gemm_grid, gemm_block, GEMM_SMEM>>>(x, Wv, bv, nullptr, 2);

    flash_attn_tc<<<dim3(T_ / 128, B_ * H_), 256, FA_SMEM>>>();

    gemm_tf32<<<gemm_grid, gemm_block, GEMM_SMEM>>>(nullptr, Wp, bp, out, 3);
}